// round 17
// baseline (speedup 1.0000x reference)
#include <cuda_runtime.h>
#include <cuda_fp16.h>
#include <cstdint>

#define BATCH 4
#define HEADS 8
#define SEQ   3137          // 1 cls + 56*56
#define HD    32
#define CDIM  256
#define HW    56
#define NPIX  (HW*HW)       // 3136
#define MTOT  (BATCH*SEQ)   // 12548
#define QKV_N 768

// ---------------- bf16 / fp16 mma helpers ----------------------------------
__device__ __forceinline__ void split_bf16(float f0, float f1,
                                           unsigned &big, unsigned &sml) {
    asm("cvt.rn.bf16x2.f32 %0, %1, %2;" : "=r"(big) : "f"(f1), "f"(f0));
    float r0 = f0 - __uint_as_float(big << 16);
    float r1 = f1 - __uint_as_float(big & 0xffff0000u);
    asm("cvt.rn.bf16x2.f32 %0, %1, %2;" : "=r"(sml) : "f"(r1), "f"(r0));
}
__device__ __forceinline__ unsigned pack_f16(float f0, float f1) {
    unsigned r; asm("cvt.rn.f16x2.f32 %0, %1, %2;" : "=r"(r) : "f"(f1), "f"(f0));
    return r;
}
__device__ __forceinline__ void split_f16(float f0, float f1,
                                          unsigned &big, unsigned &sml) {
    big = pack_f16(f0, f1);
    __half2 h = *reinterpret_cast<__half2*>(&big);
    float2 bf = __half22float2(h);
    sml = pack_f16(f0 - bf.x, f1 - bf.y);
}
__device__ __forceinline__ void mma_bf16(float c[4], const unsigned a[4],
                                         unsigned b0, unsigned b1) {
    asm volatile(
        "mma.sync.aligned.m16n8k16.row.col.f32.bf16.bf16.f32 "
        "{%0,%1,%2,%3}, {%4,%5,%6,%7}, {%8,%9}, {%0,%1,%2,%3};"
        : "+f"(c[0]), "+f"(c[1]), "+f"(c[2]), "+f"(c[3])
        : "r"(a[0]), "r"(a[1]), "r"(a[2]), "r"(a[3]), "r"(b0), "r"(b1));
}
__device__ __forceinline__ void mma_f16(float c[4], const unsigned a[4],
                                        unsigned b0, unsigned b1) {
    asm volatile(
        "mma.sync.aligned.m16n8k16.row.col.f32.f16.f16.f32 "
        "{%0,%1,%2,%3}, {%4,%5,%6,%7}, {%8,%9}, {%0,%1,%2,%3};"
        : "+f"(c[0]), "+f"(c[1]), "+f"(c[2]), "+f"(c[3])
        : "r"(a[0]), "r"(a[1]), "r"(a[2]), "r"(a[3]), "r"(b0), "r"(b1));
}
__device__ __forceinline__ float ex2(float x) {
    float r; asm("ex2.approx.f32 %0, %1;" : "=f"(r) : "f"(x)); return r;
}

// ---------------- scratch (device globals; no allocation allowed) ----------
__device__ float g_Q[(size_t)BATCH*HEADS*SEQ*HD];
__device__ float g_K[(size_t)BATCH*HEADS*SEQ*HD];
__device__ float g_V[(size_t)BATCH*HEADS*SEQ*HD];
__device__ float g_O[(size_t)BATCH*SEQ*CDIM];

// ---------------------------------------------------------------------------
// Kernel 1: QKV GEMM on tensor cores (bf16 3-pass). M=12548, N=768, K=256.
// Single-buffer W staging (R15 form: low regs, 2 barriers/iter).
// Q pre-scaled by 32^-0.5 * log2(e) (log2-domain softmax downstream).
// ---------------------------------------------------------------------------
__global__ __launch_bounds__(128) void qkv_gemm_tc_kernel(
    const float* __restrict__ x, const float* __restrict__ cls,
    const float* __restrict__ w)
{
    __shared__ float WP[16 * 32 * 4];   // 8 KB

    const int t    = threadIdx.x;
    const int warp = t >> 5;
    const int lane = t & 31;
    const int g    = lane >> 2;
    const int tq   = lane & 3;

    const int rowBase = blockIdx.x * 64;
    const int colBase = blockIdx.y * 128;

    const int r0 = rowBase + warp * 16 + g;
    const int r1 = r0 + 8;
    int r0c = r0 < MTOT ? r0 : MTOT - 1;
    int r1c = r1 < MTOT ? r1 : MTOT - 1;

    const float* arow0;
    const float* arow1;
    {
        int b0 = r0c / SEQ, s0 = r0c % SEQ;
        arow0 = (s0 == 0) ? (cls + (size_t)b0 * CDIM)
                          : (x + ((size_t)b0 * NPIX + (s0 - 1)) * CDIM);
        int b1 = r1c / SEQ, s1 = r1c % SEQ;
        arow1 = (s1 == 0) ? (cls + (size_t)b1 * CDIM)
                          : (x + ((size_t)b1 * NPIX + (s1 - 1)) * CDIM);
    }

    float acc[16][4];
#pragma unroll
    for (int nt = 0; nt < 16; nt++) {
        acc[nt][0] = 0.f; acc[nt][1] = 0.f; acc[nt][2] = 0.f; acc[nt][3] = 0.f;
    }

    float2 ast[2][4];
    float2 wst[2][8];

    {
        ast[0][0] = *(const float2*)(arow0 + 2 * tq);
        ast[0][1] = *(const float2*)(arow1 + 2 * tq);
        ast[0][2] = *(const float2*)(arow0 + 2 * tq + 8);
        ast[0][3] = *(const float2*)(arow1 + 2 * tq + 8);
#pragma unroll
        for (int ln = 0; ln < 4; ln++) {
            const float* wr = w + (size_t)(colBase + (warp * 4 + ln) * 8 + g) * CDIM + 2 * tq;
            wst[0][2 * ln]     = *(const float2*)wr;
            wst[0][2 * ln + 1] = *(const float2*)(wr + 8);
        }
    }

#pragma unroll
    for (int iter = 0; iter < 16; iter++) {
        const int cur = iter & 1, nxt = cur ^ 1;
        __syncthreads();
#pragma unroll
        for (int ln = 0; ln < 4; ln++) {
            unsigned b01, s01, b89, s89;
            split_bf16(wst[cur][2 * ln].x,     wst[cur][2 * ln].y,     b01, s01);
            split_bf16(wst[cur][2 * ln + 1].x, wst[cur][2 * ln + 1].y, b89, s89);
            *(float4*)&WP[(((warp * 4 + ln) * 32) + lane) * 4] =
                make_float4(__uint_as_float(b01), __uint_as_float(b89),
                            __uint_as_float(s01), __uint_as_float(s89));
        }
        __syncthreads();

        if (iter < 15) {
            int k0 = 16 * (iter + 1);
            ast[nxt][0] = *(const float2*)(arow0 + k0 + 2 * tq);
            ast[nxt][1] = *(const float2*)(arow1 + k0 + 2 * tq);
            ast[nxt][2] = *(const float2*)(arow0 + k0 + 2 * tq + 8);
            ast[nxt][3] = *(const float2*)(arow1 + k0 + 2 * tq + 8);
#pragma unroll
            for (int ln = 0; ln < 4; ln++) {
                const float* wr = w + (size_t)(colBase + (warp * 4 + ln) * 8 + g) * CDIM + k0 + 2 * tq;
                wst[nxt][2 * ln]     = *(const float2*)wr;
                wst[nxt][2 * ln + 1] = *(const float2*)(wr + 8);
            }
        }

        unsigned ab[4], as[4];
        split_bf16(ast[cur][0].x, ast[cur][0].y, ab[0], as[0]);
        split_bf16(ast[cur][1].x, ast[cur][1].y, ab[1], as[1]);
        split_bf16(ast[cur][2].x, ast[cur][2].y, ab[2], as[2]);
        split_bf16(ast[cur][3].x, ast[cur][3].y, ab[3], as[3]);

#pragma unroll
        for (int nt = 0; nt < 16; nt++) {
            float4 wf = *(const float4*)&WP[((nt * 32) + lane) * 4];
            unsigned wb0 = __float_as_uint(wf.x), wb1 = __float_as_uint(wf.y);
            unsigned ws0 = __float_as_uint(wf.z), ws1 = __float_as_uint(wf.w);
            mma_bf16(acc[nt], ab, wb0, wb1);
            mma_bf16(acc[nt], as, wb0, wb1);
            mma_bf16(acc[nt], ab, ws0, ws1);
        }
    }

    // epilogue: scatter into g_Q (scaled, log2 domain) / g_K / g_V
    const float scale = 0.2550348293228297f;   // 32^-0.5 * log2(e)
#pragma unroll
    for (int half = 0; half < 2; half++) {
        int r = half ? r1 : r0;
        if (r >= MTOT) continue;
        int b = r / SEQ, s = r % SEQ;
#pragma unroll
        for (int nt = 0; nt < 16; nt++) {
            int col   = colBase + nt * 8 + 2 * tq;
            int which = col >> 8;
            int f     = col & 255;
            int head  = f >> 5;
            int d     = f & 31;
            size_t dst = (((size_t)(b * HEADS + head)) * SEQ + s) * HD + d;
            float v0 = acc[nt][half * 2 + 0];
            float v1 = acc[nt][half * 2 + 1];
            if (which == 0) {
                *(float2*)&g_Q[dst] = make_float2(v0 * scale, v1 * scale);
            } else if (which == 1) {
                *(float2*)&g_K[dst] = make_float2(v0, v1);
            } else {
                *(float2*)&g_V[dst] = make_float2(v0, v1);
            }
        }
    }
}

// ---------------------------------------------------------------------------
// Flash attention staging helpers (block-wide: 4 warps cover a 64-key chunk)
// ---------------------------------------------------------------------------
__device__ __forceinline__ void load_k_raw(const float* __restrict__ Kg,
                                           int kbase, int warp, int g, int tq,
                                           float2 kst2[2][4]) {
#pragma unroll
    for (int ln = 0; ln < 2; ln++) {
        int key = kbase + warp * 16 + ln * 8 + g;
        if (key > SEQ - 1) key = SEQ - 1;
        const float* kr = Kg + (size_t)key * HD + 2 * tq;
        kst2[ln][0] = *(const float2*)(kr);
        kst2[ln][1] = *(const float2*)(kr + 8);
        kst2[ln][2] = *(const float2*)(kr + 16);
        kst2[ln][3] = *(const float2*)(kr + 24);
    }
}
__device__ __forceinline__ void load_v_raw(const float* __restrict__ Vg,
                                           int kbase, int warp, int g, int tq,
                                           float vst[4][4]) {
    int k0 = kbase + 16 * warp + 2 * tq;
    int ka = k0, kb2 = k0 + 1, kc2 = k0 + 8, kd = k0 + 9;
    if (ka  > SEQ - 1) ka  = SEQ - 1;
    if (kb2 > SEQ - 1) kb2 = SEQ - 1;
    if (kc2 > SEQ - 1) kc2 = SEQ - 1;
    if (kd  > SEQ - 1) kd  = SEQ - 1;
#pragma unroll
    for (int ln = 0; ln < 4; ln++) {
        int d = ln * 8 + g;
        vst[ln][0] = Vg[(size_t)ka  * HD + d];
        vst[ln][1] = Vg[(size_t)kb2 * HD + d];
        vst[ln][2] = Vg[(size_t)kc2 * HD + d];
        vst[ln][3] = Vg[(size_t)kd  * HD + d];
    }
}
__device__ __forceinline__ void store_tiles(uint4* __restrict__ KPb,
                                            uint4* __restrict__ VPb,
                                            int warp, int lane,
                                            const float2 kst2[2][4],
                                            const float vst[4][4]) {
#pragma unroll
    for (int ln = 0; ln < 2; ln++) {
#pragma unroll
        for (int kc = 0; kc < 2; kc++) {
            unsigned b01, s01, b89, s89;
            split_bf16(kst2[ln][2 * kc].x,     kst2[ln][2 * kc].y,     b01, s01);
            split_bf16(kst2[ln][2 * kc + 1].x, kst2[ln][2 * kc + 1].y, b89, s89);
            KPb[(((warp * 2 + ln) * 2 + kc) * 32) + lane] =
                make_uint4(b01, b89, s01, s89);
        }
    }
#pragma unroll
    for (int ln = 0; ln < 4; ln++) {
        unsigned vb0, vs0, vb1, vs1;
        split_f16(vst[ln][0], vst[ln][1], vb0, vs0);
        split_f16(vst[ln][2], vst[ln][3], vb1, vs1);
        VPb[((warp * 4 + ln) * 32) + lane] = make_uint4(vb0, vb1, vs0, vs1);
    }
}

// ---------------------------------------------------------------------------
// Kernel 2: flash attention. m16 per warp (64 q/block), 12 warps/SM via
// __launch_bounds__(128,3). QK bf16 3-pass; PV fp16 (P single, V 2-split);
// log2-domain softmax; double-buffered smem tiles, ONE barrier per chunk;
// pipelined gmem staging.
// ---------------------------------------------------------------------------
__global__ __launch_bounds__(128, 3) void flash_attn_tc_kernel()
{
    const int b  = blockIdx.z;
    const int h  = blockIdx.y;
    const int qt = blockIdx.x;

    const float* Qg = g_Q + ((size_t)(b * HEADS + h)) * SEQ * HD;
    const float* Kg = g_K + ((size_t)(b * HEADS + h)) * SEQ * HD;
    const float* Vg = g_V + ((size_t)(b * HEADS + h)) * SEQ * HD;

    __shared__ uint4 KP[2][16 * 32];   // 8 KB per buffer
    __shared__ uint4 VP[2][16 * 32];

    const int t    = threadIdx.x;
    const int warp = t >> 5;
    const int lane = t & 31;
    const int g    = lane >> 2;
    const int tq   = lane & 3;

    const int qbase = qt * 64 + warp * 16;

    // ---- resident Q fragments (bf16 big/small), 2 k16-chunks ----
    unsigned qb[2][4], qs[2][4];
    {
        int r0 = qbase + g;     if (r0 > SEQ - 1) r0 = SEQ - 1;
        int r1 = qbase + g + 8; if (r1 > SEQ - 1) r1 = SEQ - 1;
#pragma unroll
        for (int kc = 0; kc < 2; kc++) {
            const float* p0 = Qg + (size_t)r0 * HD + 16 * kc + 2 * tq;
            const float* p1 = Qg + (size_t)r1 * HD + 16 * kc + 2 * tq;
            float2 a = *(const float2*)p0;
            float2 c = *(const float2*)(p0 + 8);
            float2 d = *(const float2*)(p1 + 8);
            float2 e = *(const float2*)p1;
            split_bf16(a.x, a.y, qb[kc][0], qs[kc][0]);
            split_bf16(e.x, e.y, qb[kc][1], qs[kc][1]);
            split_bf16(c.x, c.y, qb[kc][2], qs[kc][2]);
            split_bf16(d.x, d.y, qb[kc][3], qs[kc][3]);
        }
    }

    float O[4][4] = {};
    float m0 = -1e30f, m1 = -1e30f;
    float l0 = 0.f, l1 = 0.f;

    const int NKT = (SEQ + 63) / 64;    // 50

    float2 kst2[2][4];
    float  vst[4][4];

    // ---- prologue: chunk0 -> buf0; chunk1 raw into regs ----
    load_k_raw(Kg, 0, warp, g, tq, kst2);
    load_v_raw(Vg, 0, warp, g, tq, vst);
    store_tiles(KP[0], VP[0], warp, lane, kst2, vst);
    if (NKT > 1) {
        load_k_raw(Kg, 64, warp, g, tq, kst2);
        load_v_raw(Vg, 64, warp, g, tq, vst);
    }
    __syncthreads();

    for (int kt = 0; kt < NKT; kt++) {
        const int kbase = kt * 64;
        const int cur = kt & 1, nxt = cur ^ 1;

        // ---- S = Q K^T from KP[cur] : 8 n-tiles, 2 k16-chunks, 3-pass bf16 -
        float s[8][4];
#pragma unroll
        for (int nt = 0; nt < 8; nt++) {
            s[nt][0] = 0.f; s[nt][1] = 0.f; s[nt][2] = 0.f; s[nt][3] = 0.f;
#pragma unroll
            for (int kc = 0; kc < 2; kc++) {
                uint4 kf = KP[cur][((nt * 2 + kc) * 32) + lane];
                mma_bf16(s[nt], qb[kc], kf.x, kf.y);
                mma_bf16(s[nt], qs[kc], kf.x, kf.y);
                mma_bf16(s[nt], qb[kc], kf.z, kf.w);
            }
        }

        // ---- stage chunk kt+1 into idle buffer; prefetch chunk kt+2 ----
        if (kt + 1 < NKT) {
            store_tiles(KP[nxt], VP[nxt], warp, lane, kst2, vst);
            if (kt + 2 < NKT) {
                load_k_raw(Kg, (kt + 2) * 64, warp, g, tq, kst2);
                load_v_raw(Vg, (kt + 2) * 64, warp, g, tq, vst);
            }
        }

        // ---- mask invalid keys (only last chunk) ----
        if (kbase + 64 > SEQ) {
#pragma unroll
            for (int nt = 0; nt < 8; nt++) {
                int c = kbase + nt * 8 + 2 * tq;
                if (c     >= SEQ) { s[nt][0] = -1e30f; s[nt][2] = -1e30f; }
                if (c + 1 >= SEQ) { s[nt][1] = -1e30f; s[nt][3] = -1e30f; }
            }
        }

        // ---- online softmax (log2 domain, raw ex2) ----
        {
            float mx0 = -1e30f, mx1 = -1e30f;
#pragma unroll
            for (int nt = 0; nt < 8; nt++) {
                mx0 = fmaxf(mx0, fmaxf(s[nt][0], s[nt][1]));
                mx1 = fmaxf(mx1, fmaxf(s[nt][2], s[nt][3]));
            }
            mx0 = fmaxf(mx0, __shfl_xor_sync(0xffffffffu, mx0, 1));
            mx0 = fmaxf(mx0, __shfl_xor_sync(0xffffffffu, mx0, 2));
            mx1 = fmaxf(mx1, __shfl_xor_sync(0xffffffffu, mx1, 1));
            mx1 = fmaxf(mx1, __shfl_xor_sync(0xffffffffu, mx1, 2));
            float mn0 = fmaxf(m0, mx0);
            float mn1 = fmaxf(m1, mx1);
            float corr0 = ex2(m0 - mn0);
            float corr1 = ex2(m1 - mn1);

            float ls0 = 0.f, ls1 = 0.f;
#pragma unroll
            for (int nt = 0; nt < 8; nt++) {
                s[nt][0] = ex2(s[nt][0] - mn0);
                s[nt][1] = ex2(s[nt][1] - mn0);
                s[nt][2] = ex2(s[nt][2] - mn1);
                s[nt][3] = ex2(s[nt][3] - mn1);
                ls0 += s[nt][0] + s[nt][1];
                ls1 += s[nt][2] + s[nt][3];
            }
            ls0 += __shfl_xor_sync(0xffffffffu, ls0, 1);
            ls0 += __shfl_xor_sync(0xffffffffu, ls0, 2);
            ls1 += __shfl_xor_sync(0xffffffffu, ls1, 1);
            ls1 += __shfl_xor_sync(0xffffffffu, ls1, 2);
            l0 = l0 * corr0 + ls0;  m0 = mn0;
            l1 = l1 * corr1 + ls1;  m1 = mn1;

#pragma unroll
            for (int nt = 0; nt < 4; nt++) {
                O[nt][0] *= corr0; O[nt][1] *= corr0;
                O[nt][2] *= corr1; O[nt][3] *= corr1;
            }
        }

        // ---- O += P V : P single fp16 (own C-frag), V 2-split fp16 ----
#pragma unroll
        for (int kc = 0; kc < 4; kc++) {
            unsigned pp[4];
            pp[0] = pack_f16(s[2*kc][0],   s[2*kc][1]);
            pp[1] = pack_f16(s[2*kc][2],   s[2*kc][3]);
            pp[2] = pack_f16(s[2*kc+1][0], s[2*kc+1][1]);
            pp[3] = pack_f16(s[2*kc+1][2], s[2*kc+1][3]);
#pragma unroll
            for (int nt = 0; nt < 4; nt++) {
                uint4 vf = VP[cur][((kc * 4 + nt) * 32) + lane];
                mma_f16(O[nt], pp, vf.x, vf.y);   // P * V_big
                mma_f16(O[nt], pp, vf.z, vf.w);   // P * V_small
            }
        }
        __syncthreads();
    }

    // ---- epilogue ----
    {
        float inv0 = 1.f / l0, inv1 = 1.f / l1;
        int r0 = qbase + g;
        int r1 = qbase + g + 8;
#pragma unroll
        for (int nt = 0; nt < 4; nt++) {
            int col = h * HD + nt * 8 + 2 * tq;
            if (r0 < SEQ) {
                float2 v = make_float2(O[nt][0] * inv0, O[nt][1] * inv0);
                *(float2*)&g_O[((size_t)b * SEQ + r0) * CDIM + col] = v;
            }
            if (r1 < SEQ) {
                float2 v = make_float2(O[nt][2] * inv1, O[nt][3] * inv1);
                *(float2*)&g_O[((size_t)b * SEQ + r1) * CDIM + col] = v;
            }
        }
    }
}

// ---------------------------------------------------------------------------
// Kernel 3: depthwise 5x5 LePE (NHWC, SAME), adds into g_O rows 1..3136.
// ---------------------------------------------------------------------------
__global__ __launch_bounds__(256) void lepe_kernel(
    const float* __restrict__ x, const float* __restrict__ w,
    const float* __restrict__ bias)
{
    __shared__ float ws[CDIM * 25];
    const int c = threadIdx.x;
    for (int idx = c; idx < CDIM * 25; idx += 256) ws[idx] = w[idx];
    __syncthreads();

    const int blk  = blockIdx.x;         // 0 .. 4*56*7-1
    const int b    = blk / (HW * 7);
    const int rem  = blk % (HW * 7);
    const int hh   = rem / 7;
    const int ww0  = (rem % 7) * 8;
    const float bc = bias[c];

#pragma unroll
    for (int p = 0; p < 8; p++) {
        int ww = ww0 + p;
        float sum = bc;
#pragma unroll
        for (int dy = 0; dy < 5; dy++) {
            int y = hh + dy - 2;
            if (y < 0 || y >= HW) continue;
#pragma unroll
            for (int dx = 0; dx < 5; dx++) {
                int xx = ww + dx - 2;
                if (xx < 0 || xx >= HW) continue;
                sum = fmaf(x[(((size_t)b * HW + y) * HW + xx) * CDIM + c],
                           ws[c * 25 + dy * 5 + dx], sum);
            }
        }
        int hw = hh * HW + ww;
        g_O[((size_t)b * SEQ + 1 + hw) * CDIM + c] += sum;
    }
}

// ---------------------------------------------------------------------------
// Kernel 4: proj GEMM on tensor cores (bf16 3-pass). M=12548, N=256, K=256.
// Single-buffer W staging (R15 form).
// ---------------------------------------------------------------------------
__global__ __launch_bounds__(128) void proj_gemm_tc_kernel(
    const float* __restrict__ w, const float* __restrict__ bias,
    float* __restrict__ out)
{
    __shared__ float WP[16 * 32 * 4];   // 8 KB

    const int t    = threadIdx.x;
    const int warp = t >> 5;
    const int lane = t & 31;
    const int g    = lane >> 2;
    const int tq   = lane & 3;

    const int rowBase = blockIdx.x * 64;
    const int colBase = blockIdx.y * 128;

    const int r0 = rowBase + warp * 16 + g;
    const int r1 = r0 + 8;
    int r0c = r0 < MTOT ? r0 : MTOT - 1;
    int r1c = r1 < MTOT ? r1 : MTOT - 1;
    const float* arow0 = g_O + (size_t)r0c * CDIM;
    const float* arow1 = g_O + (size_t)r1c * CDIM;

    float acc[16][4];
#pragma unroll
    for (int nt = 0; nt < 16; nt++) {
        acc[nt][0] = 0.f; acc[nt][1] = 0.f; acc[nt][2] = 0.f; acc[nt][3] = 0.f;
    }

    float2 ast[2][4];
    float2 wst[2][8];
    {
        ast[0][0] = *(const float2*)(arow0 + 2 * tq);
        ast[0][1] = *(const float2*)(arow1 + 2 * tq);
        ast[0][2] = *(const float2*)(arow0 + 2 * tq + 8);
        ast[0][3] = *(const float2*)(arow1 + 2 * tq + 8);
#pragma unroll
        for (int ln = 0; ln < 4; ln++) {
            const float* wr = w + (size_t)(colBase + (warp * 4 + ln) * 8 + g) * CDIM + 2 * tq;
            wst[0][2 * ln]     = *(const float2*)wr;
            wst[0][2 * ln + 1] = *(const float2*)(wr + 8);
        }
    }

#pragma unroll
    for (int iter = 0; iter < 16; iter++) {
        const int cur = iter & 1, nxt = cur ^ 1;
        __syncthreads();
#pragma unroll
        for (int ln = 0; ln < 4; ln++) {
            unsigned b01, s01, b89, s89;
            split_bf16(wst[cur][2 * ln].x,     wst[cur][2 * ln].y,     b01, s01);
            split_bf16(wst[cur][2 * ln + 1].x, wst[cur][2 * ln + 1].y, b89, s89);
            *(float4*)&WP[(((warp * 4 + ln) * 32) + lane) * 4] =
                make_float4(__uint_as_float(b01), __uint_as_float(b89),
                            __uint_as_float(s01), __uint_as_float(s89));
        }
        __syncthreads();

        if (iter < 15) {
            int k0 = 16 * (iter + 1);
            ast[nxt][0] = *(const float2*)(arow0 + k0 + 2 * tq);
            ast[nxt][1] = *(const float2*)(arow1 + k0 + 2 * tq);
            ast[nxt][2] = *(const float2*)(arow0 + k0 + 2 * tq + 8);
            ast[nxt][3] = *(const float2*)(arow1 + k0 + 2 * tq + 8);
#pragma unroll
            for (int ln = 0; ln < 4; ln++) {
                const float* wr = w + (size_t)(colBase + (warp * 4 + ln) * 8 + g) * CDIM + k0 + 2 * tq;
                wst[nxt][2 * ln]     = *(const float2*)wr;
                wst[nxt][2 * ln + 1] = *(const float2*)(wr + 8);
            }
        }

        unsigned ab[4], as[4];
        split_bf16(ast[cur][0].x, ast[cur][0].y, ab[0], as[0]);
        split_bf16(ast[cur][1].x, ast[cur][1].y, ab[1], as[1]);
        split_bf16(ast[cur][2].x, ast[cur][2].y, ab[2], as[2]);
        split_bf16(ast[cur][3].x, ast[cur][3].y, ab[3], as[3]);

#pragma unroll
        for (int nt = 0; nt < 16; nt++) {
            float4 wf = *(const float4*)&WP[((nt * 32) + lane) * 4];
            unsigned wb0 = __float_as_uint(wf.x), wb1 = __float_as_uint(wf.y);
            unsigned ws0 = __float_as_uint(wf.z), ws1 = __float_as_uint(wf.w);
            mma_bf16(acc[nt], ab, wb0, wb1);
            mma_bf16(acc[nt], as, wb0, wb1);
            mma_bf16(acc[nt], ab, ws0, ws1);
        }
    }

    const size_t cls_off = (size_t)BATCH * NPIX * CDIM;
#pragma unroll
    for (int half = 0; half < 2; half++) {
        int r = half ? r1 : r0;
        if (r >= MTOT) continue;
        int b = r / SEQ, s = r % SEQ;
#pragma unroll
        for (int nt = 0; nt < 16; nt++) {
            int col = colBase + nt * 8 + 2 * tq;
            float v0 = acc[nt][half * 2 + 0] + bias[col];
            float v1 = acc[nt][half * 2 + 1] + bias[col + 1];
            size_t dst = (s == 0)
                       ? cls_off + (size_t)b * CDIM + col
                       : ((size_t)b * NPIX + (s - 1)) * CDIM + col;
            *(float2*)&out[dst] = make_float2(v0, v1);
        }
    }
}

// ---------------------------------------------------------------------------
extern "C" void kernel_launch(void* const* d_in, const int* in_sizes, int n_in,
                              void* d_out, int out_size)
{
    const float* x      = (const float*)d_in[0];
    const float* cls    = (const float*)d_in[1];
    const float* qkv_w  = (const float*)d_in[2];
    const float* proj_w = (const float*)d_in[3];
    const float* proj_b = (const float*)d_in[4];
    const float* lepe_w = (const float*)d_in[5];
    const float* lepe_b = (const float*)d_in[6];
    float* out = (float*)d_out;

    dim3 g1((MTOT + 63) / 64, QKV_N / 128);       // 197 x 6
    qkv_gemm_tc_kernel<<<g1, 128>>>(x, cls, qkv_w);

    dim3 g2((SEQ + 63) / 64, HEADS, BATCH);       // 50 x 8 x 4
    flash_attn_tc_kernel<<<g2, 128>>>();

    lepe_kernel<<<BATCH * HW * 7, 256>>>(x, lepe_w, lepe_b);

    dim3 g4((MTOT + 63) / 64, CDIM / 128);        // 197 x 2
    proj_gemm_tc_kernel<<<g4, 128>>>(proj_w, proj_b, out);
}